// round 12
// baseline (speedup 1.0000x reference)
#include <cuda_runtime.h>
#include <cstdint>

// BilinearInteraction: out[b, p, :] = x[b, i_p, :] * (x[b, j_p, :] @ W)
//   x: [4096, 32, 64] f32, W: [64, 64] f32, out: [4096, 496, 64] f32
//   R10 frame, W moved to __constant__ (uniform LDCU in GEMM -> 0 L1 wf),
//   lane-per-row GEMM, XOR-swizzled vs, 7 CTAs/SM (3.95 waves, 56 warps).

#define NF 32
#define ED 64
#define NP 496
#define NTHREADS 256
#define NBATCH 4096
#define XSTR 17                   // xs row stride in float4

__constant__ float4 Wc4[ED * (ED / 4)];   // 16 KB: W[d][e], f4 over e

__global__ void __launch_bounds__(NTHREADS, 7)
bilinear_kernel(const float* __restrict__ x,
                float* __restrict__ out)
{
    __shared__ float4 xs4[NF * XSTR];        // 8704 B (padded rows)
    __shared__ float4 vs4[NF * (ED / 4)];    // 8192 B (XOR-swizzled cols)

    const int b   = blockIdx.x;
    const int tid = threadIdx.x;

    // ---- x prologue: padded copy ----
    {
        const float4* xg = (const float4*)(x + (size_t)b * (NF * ED));
#pragma unroll
        for (int k = 0; k < 2; k++) {
            const int idx = tid + k * NTHREADS;   // 0..511
            const int row = idx >> 4;
            const int col = idx & 15;
            xs4[row * XSTR + col] = xg[idx];
        }
    }
    __syncthreads();

    // ---- GEMM: vid[f][e] = sum_d x[f][d] * W[d][e] ----
    // lane = row f (32 rows per warp); warp w owns e in [8w, 8w+8).
    // x: LDS.128 per lane-row, conflict-free via XSTR=17 ((f+d4)&7 phases).
    // W: address uniform across the warp -> constant/uniform path, 0 L1 wf.
    // vs store: col c placed at (c ^ (f&7)) -> conflict-free STS.128.
    {
        const int lane = tid & 31;
        const int w    = tid >> 5;
        const int c0   = 2 * w;          // first of the 2 e-f4 columns

        float4 acc0 = make_float4(0.f, 0.f, 0.f, 0.f);
        float4 acc1 = make_float4(0.f, 0.f, 0.f, 0.f);

#pragma unroll 4
        for (int d4 = 0; d4 < 16; d4++) {
            const float4 xv = xs4[lane * XSTR + d4];
#pragma unroll
            for (int dd = 0; dd < 4; dd++) {
                const int d = 4 * d4 + dd;
                const float4 w0 = Wc4[d * 16 + c0];
                const float4 w1 = Wc4[d * 16 + c0 + 1];
                const float xsc = (dd == 0) ? xv.x : (dd == 1) ? xv.y :
                                  (dd == 2) ? xv.z : xv.w;
                acc0.x = fmaf(xsc, w0.x, acc0.x);
                acc0.y = fmaf(xsc, w0.y, acc0.y);
                acc0.z = fmaf(xsc, w0.z, acc0.z);
                acc0.w = fmaf(xsc, w0.w, acc0.w);
                acc1.x = fmaf(xsc, w1.x, acc1.x);
                acc1.y = fmaf(xsc, w1.y, acc1.y);
                acc1.z = fmaf(xsc, w1.z, acc1.z);
                acc1.w = fmaf(xsc, w1.w, acc1.w);
            }
        }
        const int s = lane & 7;
        vs4[lane * 16 + (c0 ^ s)]       = acc0;
        vs4[lane * 16 + ((c0 + 1) ^ s)] = acc1;
    }
    __syncthreads();

    // ---- Write phase: row-sequential streaming stores (R10) ----
    // Warp w owns rows {w, 30-w, 15-w, 15+w} (warp 0: {0, 30, 15}).
    {
        const int w    = tid >> 5;
        const int lane = tid & 31;
        const int v    = lane & 15;
        const int h    = lane >> 4;

        float4* out4 = (float4*)(out + (size_t)b * (NP * ED));

        int rows[4];
        int nrows;
        if (w == 0) {
            rows[0] = 0; rows[1] = 30; rows[2] = 15; rows[3] = 0;
            nrows = 3;
        } else {
            rows[0] = w; rows[1] = 30 - w; rows[2] = 15 - w; rows[3] = 15 + w;
            nrows = 4;
        }

#pragma unroll
        for (int r = 0; r < 4; r++) {
            if (r >= nrows) break;
            const int i = rows[r];
            const float4 a  = xs4[i * XSTR + v];
            const int cnt   = 31 - i;
            const int iters = (cnt + 1 - h) >> 1;   // exact per half-lane
            const int p0    = (i * (63 - i)) >> 1;

#pragma unroll 2
            for (int t = 0; t < iters; t++) {
                const int j = i + 1 + 2 * t + h;
                const float4 cvv = vs4[j * 16 + (v ^ (j & 7))];
                const int p = p0 + (j - i - 1);
                float4 rr;
                rr.x = a.x * cvv.x;
                rr.y = a.y * cvv.y;
                rr.z = a.z * cvv.z;
                rr.w = a.w * cvv.w;
                __stcs(out4 + p * 16 + v, rr);
            }
        }
    }
}

extern "C" void kernel_launch(void* const* d_in, const int* in_sizes, int n_in,
                              void* d_out, int out_size)
{
    const float* x = (const float*)d_in[0];
    const float* W = (const float*)d_in[1];
    float*       o = (float*)d_out;

    // W (device) -> constant bank, D2D async memcpy (graph-capturable node).
    cudaMemcpyToSymbolAsync(Wc4, W, ED * ED * sizeof(float), 0,
                            cudaMemcpyDeviceToDevice, 0);
    bilinear_kernel<<<NBATCH, NTHREADS>>>(x, o);
}

// round 13
// speedup vs baseline: 2.1244x; 2.1244x over previous
#include <cuda_runtime.h>
#include <cstdint>

// BilinearInteraction: out[b, p, :] = x[b, i_p, :] * (x[b, j_p, :] @ W)
//   x: [4096, 32, 64] f32, W: [64, 64] f32, out: [4096, 496, 64] f32
//   R10 per-CTA profile at 512 threads / 4 CTAs/SM:
//   - 592 concurrent CTAs -> 6.92 waves (tail ~1% vs 8% at 6x256)
//   - GEMM on warps 0-7 only (LSU-optimal 96 instr/warp preserved)
//   - write phase on all 16 warps, row-sequential streaming stores
//   - W via cp.async.bulk; padded xs; stcs outputs

#define NF 32
#define ED 64
#define NP 496
#define NTHREADS 512
#define NBATCH 4096
#define XSTR 17                   // xs row stride in float4

__device__ __forceinline__ unsigned smem_u32(const void* p) {
    unsigned a;
    asm("{ .reg .u64 t; cvta.to.shared.u64 t, %1; cvt.u32.u64 %0, t; }"
        : "=r"(a) : "l"(p));
    return a;
}

__global__ void __launch_bounds__(NTHREADS, 4)
bilinear_kernel(const float* __restrict__ x,
                const float* __restrict__ W,
                float* __restrict__ out)
{
    __shared__ float4 xs4[NF * XSTR];            // 8704 B (padded)
    __shared__ float4 vs4[NF * (ED / 4)];        // 8192 B
    __shared__ float4 Ws4[ED * (ED / 4)];        // 16384 B
    __shared__ __align__(8) unsigned long long mbar;

    const int b   = blockIdx.x;
    const int tid = threadIdx.x;

    // ---- mbarrier init, then W via 1D bulk copy (async proxy) ----
    if (tid == 0) {
        asm volatile("mbarrier.init.shared.b64 [%0], 1;"
                     :: "r"(smem_u32(&mbar)) : "memory");
    }
    __syncthreads();
    if (tid == 0) {
        const unsigned mb = smem_u32(&mbar);
        asm volatile("mbarrier.arrive.expect_tx.shared.b64 _, [%0], %1;"
                     :: "r"(mb), "r"(16384u) : "memory");
        asm volatile(
            "cp.async.bulk.shared::cluster.global.mbarrier::complete_tx::bytes "
            "[%0], [%1], %2, [%3];"
            :: "r"(smem_u32(Ws4)), "l"(W), "r"(16384u), "r"(mb) : "memory");
    }

    // ---- x prologue: padded copy (512 threads -> 1 f4 each) ----
    {
        const float4* xg = (const float4*)(x + (size_t)b * (NF * ED));
        const int row = tid >> 4;
        const int col = tid & 15;
        xs4[row * XSTR + col] = xg[tid];
    }
    __syncthreads();

    // ---- wait for W (acquire) ----
    {
        const unsigned mb = smem_u32(&mbar);
        unsigned done;
        asm volatile(
            "{\n\t.reg .pred p;\n\t"
            "mbarrier.try_wait.parity.acquire.cta.shared::cta.b64 p, [%1], 0;\n\t"
            "selp.b32 %0, 1, 0, p;\n\t}"
            : "=r"(done) : "r"(mb) : "memory");
        while (!done) {
            asm volatile(
                "{\n\t.reg .pred p;\n\t"
                "mbarrier.try_wait.parity.acquire.cta.shared::cta.b64 p, [%1], 0, 0x989680;\n\t"
                "selp.b32 %0, 1, 0, p;\n\t}"
                : "=r"(done) : "r"(mb) : "memory");
        }
    }

    const int w    = tid >> 5;        // 0..15
    const int lane = tid & 31;

    // ---- GEMM on warps 0-7 (exact R10 layout, LSU-optimal) ----
    // Warp w: wr = w&3 (rows 8wr..8wr+7), half = w>>2 (e-f4 cols 8h..8h+7).
    // Lane: fi = lane>>3 (row), ci = lane&7 (col). Rows f0, f0+4; col c.
    if (w < 8) {
        const int wr   = w & 3;
        const int half = w >> 2;
        const int fi   = lane >> 3;
        const int ci   = lane & 7;
        const int f0   = 8 * wr + fi;
        const int c    = 8 * half + ci;

        float4 acc0 = make_float4(0.f, 0.f, 0.f, 0.f);
        float4 acc1 = make_float4(0.f, 0.f, 0.f, 0.f);

#pragma unroll 4
        for (int d4 = 0; d4 < 16; d4++) {
            const float4 xv0 = xs4[f0 * XSTR + d4];
            const float4 xv1 = xs4[(f0 + 4) * XSTR + d4];
#pragma unroll
            for (int dd = 0; dd < 4; dd++) {
                const float4 wv = Ws4[(4 * d4 + dd) * 16 + c];
                const float xa = (dd == 0) ? xv0.x : (dd == 1) ? xv0.y :
                                 (dd == 2) ? xv0.z : xv0.w;
                const float xb = (dd == 0) ? xv1.x : (dd == 1) ? xv1.y :
                                 (dd == 2) ? xv1.z : xv1.w;
                acc0.x = fmaf(xa, wv.x, acc0.x);
                acc0.y = fmaf(xa, wv.y, acc0.y);
                acc0.z = fmaf(xa, wv.z, acc0.z);
                acc0.w = fmaf(xa, wv.w, acc0.w);
                acc1.x = fmaf(xb, wv.x, acc1.x);
                acc1.y = fmaf(xb, wv.y, acc1.y);
                acc1.z = fmaf(xb, wv.z, acc1.z);
                acc1.w = fmaf(xb, wv.w, acc1.w);
            }
        }
        vs4[f0 * 16 + c]       = acc0;
        vs4[(f0 + 4) * 16 + c] = acc1;
    }
    __syncthreads();

    // ---- Write phase: 16 warps, row-sequential streaming stores ----
    // Warp w < 15: rows {w, 30-w} (32 pairs); warp 15: row 15 (16 pairs).
    {
        const int v = lane & 15;
        const int h = lane >> 4;

        float4* out4 = (float4*)(out + (size_t)b * (NP * ED));

        int rows[2];
        int nrows;
        if (w == 15) {
            rows[0] = 15; rows[1] = 15;
            nrows = 1;
        } else {
            rows[0] = w; rows[1] = 30 - w;
            nrows = 2;
        }

#pragma unroll
        for (int r = 0; r < 2; r++) {
            if (r >= nrows) break;
            const int i = rows[r];
            const float4 a  = xs4[i * XSTR + v];
            const int cnt   = 31 - i;
            const int iters = (cnt + 1 - h) >> 1;   // exact per half-lane
            const int p0    = (i * (63 - i)) >> 1;

#pragma unroll 2
            for (int t = 0; t < iters; t++) {
                const int j = i + 1 + 2 * t + h;
                const float4 cvv = vs4[j * 16 + v];
                const int p = p0 + (j - i - 1);
                float4 rr;
                rr.x = a.x * cvv.x;
                rr.y = a.y * cvv.y;
                rr.z = a.z * cvv.z;
                rr.w = a.w * cvv.w;
                __stcs(out4 + p * 16 + v, rr);
            }
        }
    }
}

extern "C" void kernel_launch(void* const* d_in, const int* in_sizes, int n_in,
                              void* d_out, int out_size)
{
    const float* x = (const float*)d_in[0];
    const float* W = (const float*)d_in[1];
    float*       o = (float*)d_out;
    bilinear_kernel<<<NBATCH, NTHREADS>>>(x, W, o);
}